// round 7
// baseline (speedup 1.0000x reference)
#include <cuda_runtime.h>
#include <cuda_fp16.h>
#include <cstdint>

// Problem-size maxima (fixed by the reference generator).
static constexpr int NMAX = 1000000;
static constexpr int EMAX = 12000000;
static constexpr int GMAX = 1000;

// Double-buffered node state, 8 fp16 per node (16B, one LDG.128 per gather).
__device__ uint4 g_hA[NMAX];
__device__ uint4 g_hB[NMAX];
// Dst-grouped edge records: {src, ea01, ea23, ea45} (fp16 pairs), 16B each.
__device__ uint4 g_rec[EMAX];
__device__ int   g_cnt[NMAX];
__device__ int   g_off[NMAX];
__device__ int   g_cur[NMAX];
__device__ int   g_cursor;
__device__ float g_gsum[GMAX];
__device__ float g_gcnt[GMAX];

__device__ __forceinline__ unsigned f2h2(float a, float b) {
    __half2 p = __floats2half2_rn(a, b);
    return *reinterpret_cast<unsigned*>(&p);
}
__device__ __forceinline__ float2 h22f2(unsigned u) {
    return __half22float2(*reinterpret_cast<__half2*>(&u));
}
// h layout: {p01, p23, p45, 0}
__device__ __forceinline__ uint4 pack_h(const float* v) {
    return make_uint4(f2h2(v[0], v[1]), f2h2(v[2], v[3]), f2h2(v[4], v[5]), 0u);
}
__device__ __forceinline__ void unpack_h(uint4 v, float* a) {
    float2 f0 = h22f2(v.x), f1 = h22f2(v.y), f2 = h22f2(v.z);
    a[0] = f0.x; a[1] = f0.y; a[2] = f1.x; a[3] = f1.y; a[4] = f2.x; a[5] = f2.y;
}

// ---------------------------------------------------------------------------
// Init: hA <- fp16(x); cnt <- 0; pool accumulators + cursor <- 0.
// ---------------------------------------------------------------------------
__global__ __launch_bounds__(256) void init_kernel(const float* __restrict__ x,
                                                   int N, int G) {
    int i = blockIdx.x * 256 + threadIdx.x;
    if (i < N) {
        const float2* xp = reinterpret_cast<const float2*>(x + (size_t)i * 6);
        float2 a = __ldcs(xp + 0);
        float2 b = __ldcs(xp + 1);
        float2 c = __ldcs(xp + 2);
        float v[6] = {a.x, a.y, b.x, b.y, c.x, c.y};
        g_hA[i] = pack_h(v);
        g_cnt[i] = 0;
    }
    if (i < G) { g_gsum[i] = 0.f; g_gcnt[i] = 0.f; }
    if (i == 0) g_cursor = 0;
}

// ---------------------------------------------------------------------------
// Histogram of in-degrees.
// ---------------------------------------------------------------------------
__global__ __launch_bounds__(256) void hist_kernel(const int* __restrict__ ei,
                                                   int E) {
    int e = blockIdx.x * 256 + threadIdx.x;
    if (e >= E) return;
    int d = __ldcs(ei + (size_t)E + e);
    atomicAdd(&g_cnt[d], 1);
}

// ---------------------------------------------------------------------------
// Range allocation: per-block exclusive scan of cnt, one global atomic per
// block claims the block's span. (Range ORDER across blocks is arbitrary;
// only per-dst contiguity matters.)
// ---------------------------------------------------------------------------
__global__ __launch_bounds__(256) void alloc_kernel(int N) {
    int i = blockIdx.x * 256 + threadIdx.x;
    int lane = threadIdx.x & 31, wid = threadIdx.x >> 5;
    int v = (i < N) ? g_cnt[i] : 0;
    int inc = v;
#pragma unroll
    for (int o = 1; o < 32; o <<= 1) {
        int u = __shfl_up_sync(0xFFFFFFFFu, inc, o);
        if (lane >= o) inc += u;
    }
    __shared__ int wsum[8], wpre[8], sbase;
    if (lane == 31) wsum[wid] = inc;
    __syncthreads();
    if (threadIdx.x < 8) {
        int w = wsum[threadIdx.x];
        int winc = w;
#pragma unroll
        for (int o = 1; o < 8; o <<= 1) {
            int u = __shfl_up_sync(0x000000FFu, winc, o);
            if (threadIdx.x >= o) winc += u;
        }
        wpre[threadIdx.x] = winc - w;
        if (threadIdx.x == 7) sbase = atomicAdd(&g_cursor, winc);
    }
    __syncthreads();
    int base = sbase + wpre[wid] + (inc - v);
    if (i < N) { g_off[i] = base; g_cur[i] = base; }
}

// ---------------------------------------------------------------------------
// Scatter edges into dst-grouped records {src, fp16 edge_attr}.
// ---------------------------------------------------------------------------
__global__ __launch_bounds__(256) void scatter_kernel(const int* __restrict__ ei,
                                                      const float* __restrict__ ea,
                                                      int E) {
    int e = blockIdx.x * 256 + threadIdx.x;
    if (e >= E) return;
    int s = __ldcs(ei + e);
    int d = __ldcs(ei + (size_t)E + e);
    const float2* ep = reinterpret_cast<const float2*>(ea + (size_t)e * 6);
    float2 e0 = __ldcs(ep + 0);
    float2 e1 = __ldcs(ep + 1);
    float2 e2 = __ldcs(ep + 2);
    int p = atomicAdd(&g_cur[d], 1);
    uint4 r = make_uint4((unsigned)s, f2h2(e0.x, e0.y),
                         f2h2(e1.x, e1.y), f2h2(e2.x, e2.y));
    __stcs(&g_rec[p], r);
}

// ---------------------------------------------------------------------------
// Fused GINE layer (pull): for node i, acc = sum relu(h[src]+e) over
// in-edges (fp32, no atomics), then h_out = relu((h_in + acc) @ W + b).
// AtoB selects the h double-buffer direction.
// ---------------------------------------------------------------------------
template <bool AtoB>
__global__ __launch_bounds__(256) void layer_kernel(const float* __restrict__ W,
                                                    const float* __restrict__ b,
                                                    int N) {
    __shared__ float sW[36];
    __shared__ float sb[6];
    if (threadIdx.x < 36) sW[threadIdx.x] = W[threadIdx.x];
    if (threadIdx.x < 6)  sb[threadIdx.x] = b[threadIdx.x];
    __syncthreads();

    int i = blockIdx.x * 256 + threadIdx.x;
    if (i >= N) return;
    const uint4* hin = AtoB ? g_hA : g_hB;
    uint4*       hout = AtoB ? g_hB : g_hA;

    float h[6];
    unpack_h(__ldg(&hin[i]), h);
    float acc[6] = {0.f, 0.f, 0.f, 0.f, 0.f, 0.f};

    int k0 = g_off[i], kn = g_cnt[i];
    for (int k = k0; k < k0 + kn; k++) {
        uint4 r = __ldg(&g_rec[k]);
        float hs[6];
        unpack_h(__ldg(&hin[r.x]), hs);
        float2 e0 = h22f2(r.y), e1 = h22f2(r.z), e2 = h22f2(r.w);
        acc[0] += fmaxf(hs[0] + e0.x, 0.f);
        acc[1] += fmaxf(hs[1] + e0.y, 0.f);
        acc[2] += fmaxf(hs[2] + e1.x, 0.f);
        acc[3] += fmaxf(hs[3] + e1.y, 0.f);
        acc[4] += fmaxf(hs[4] + e2.x, 0.f);
        acc[5] += fmaxf(hs[5] + e2.y, 0.f);
    }

    float t[6], y[6];
#pragma unroll
    for (int k = 0; k < 6; k++) t[k] = h[k] + acc[k];
#pragma unroll
    for (int j = 0; j < 6; j++) {
        float a = sb[j];
#pragma unroll
        for (int k = 0; k < 6; k++) a = fmaf(t[k], sW[k * 6 + j], a);
        y[j] = fmaxf(a, 0.f);
    }
    hout[i] = pack_h(y);
}

// ---------------------------------------------------------------------------
// Layer 3 fused with pooling head: y = (h+acc)@W3+b3 (no relu); s = y.Wl;
// pooled@Wl = (sum s)/cnt per graph. batch sorted -> warp-segmented atomics.
// Reads g_hA (the L2 output buffer).
// ---------------------------------------------------------------------------
__global__ __launch_bounds__(256) void layer3_kernel(const float* __restrict__ W,
                                                     const float* __restrict__ b,
                                                     const float* __restrict__ Wl,
                                                     const int* __restrict__ batch,
                                                     int N) {
    __shared__ float sW[36];
    __shared__ float sb[6];
    __shared__ float sWl[6];
    if (threadIdx.x < 36) sW[threadIdx.x] = W[threadIdx.x];
    if (threadIdx.x < 6) { sb[threadIdx.x] = b[threadIdx.x]; sWl[threadIdx.x] = Wl[threadIdx.x]; }
    __syncthreads();

    int i = blockIdx.x * 256 + threadIdx.x;
    float s = 0.f, c = 0.f;
    int g = -1;
    if (i < N) {
        float h[6];
        unpack_h(__ldg(&g_hA[i]), h);
        float acc[6] = {0.f, 0.f, 0.f, 0.f, 0.f, 0.f};
        int k0 = g_off[i], kn = g_cnt[i];
        for (int k = k0; k < k0 + kn; k++) {
            uint4 r = __ldg(&g_rec[k]);
            float hs[6];
            unpack_h(__ldg(&g_hA[r.x]), hs);
            float2 e0 = h22f2(r.y), e1 = h22f2(r.z), e2 = h22f2(r.w);
            acc[0] += fmaxf(hs[0] + e0.x, 0.f);
            acc[1] += fmaxf(hs[1] + e0.y, 0.f);
            acc[2] += fmaxf(hs[2] + e1.x, 0.f);
            acc[3] += fmaxf(hs[3] + e1.y, 0.f);
            acc[4] += fmaxf(hs[4] + e2.x, 0.f);
            acc[5] += fmaxf(hs[5] + e2.y, 0.f);
        }
        float t[6];
#pragma unroll
        for (int k = 0; k < 6; k++) t[k] = h[k] + acc[k];
#pragma unroll
        for (int j = 0; j < 6; j++) {
            float a = sb[j];
#pragma unroll
            for (int k = 0; k < 6; k++) a = fmaf(t[k], sW[k * 6 + j], a);
            s = fmaf(a, sWl[j], s);
        }
        c = 1.f;
        g = __ldg(batch + i);
    }

    int lane = threadIdx.x & 31;
#pragma unroll
    for (int off = 1; off < 32; off <<= 1) {
        float ov = __shfl_down_sync(0xFFFFFFFFu, s, off);
        float oc = __shfl_down_sync(0xFFFFFFFFu, c, off);
        int   og = __shfl_down_sync(0xFFFFFFFFu, g, off);
        if (lane + off < 32 && og == g) { s += ov; c += oc; }
    }
    int gprev = __shfl_up_sync(0xFFFFFFFFu, g, 1);
    bool head = (lane == 0) || (gprev != g);
    if (head && g >= 0) {
        atomicAdd(&g_gsum[g], s);
        atomicAdd(&g_gcnt[g], c);
    }
}

// ---------------------------------------------------------------------------
// Finalize: out[g] = gsum[g] / max(cnt, 1) + bl
// ---------------------------------------------------------------------------
__global__ __launch_bounds__(256) void final_kernel(const float* __restrict__ bl,
                                                    float* __restrict__ out, int G) {
    int g = blockIdx.x * 256 + threadIdx.x;
    if (g < G) out[g] = g_gsum[g] / fmaxf(g_gcnt[g], 1.f) + bl[0];
}

// ---------------------------------------------------------------------------
extern "C" void kernel_launch(void* const* d_in, const int* in_sizes, int n_in,
                              void* d_out, int out_size) {
    const float* x     = (const float*)d_in[0];
    const int*   ei    = (const int*)d_in[1];     // int32 (JAX x64 disabled)
    const float* ea    = (const float*)d_in[2];
    const int*   batch = (const int*)d_in[3];     // int32
    const float* W1 = (const float*)d_in[4];
    const float* b1 = (const float*)d_in[5];
    const float* W2 = (const float*)d_in[6];
    const float* b2 = (const float*)d_in[7];
    const float* W3 = (const float*)d_in[8];
    const float* b3 = (const float*)d_in[9];
    const float* Wl = (const float*)d_in[10];
    const float* bl = (const float*)d_in[11];
    float* out = (float*)d_out;

    int N = in_sizes[0] / 6;   // x is [N, 6]
    int E = in_sizes[2] / 6;   // edge_attr is [E, 6]
    int G = out_size;          // out is [G, 1]

    int nb = (N + 255) / 256;
    int eb = (E + 255) / 256;
    int gb = (G + 255) / 256;

    // Prepass: build dst-grouped edge records (amortized over 3 layers).
    init_kernel<<<nb, 256>>>(x, N, G);
    hist_kernel<<<eb, 256>>>(ei, E);
    alloc_kernel<<<nb, 256>>>(N);
    scatter_kernel<<<eb, 256>>>(ei, ea, E);

    // Three fused pull layers (h: A->B->A, layer 3 reads A and pools).
    layer_kernel<true><<<nb, 256>>>(W1, b1, N);
    layer_kernel<false><<<nb, 256>>>(W2, b2, N);
    layer3_kernel<<<nb, 256>>>(W3, b3, Wl, batch, N);

    final_kernel<<<gb, 256>>>(bl, out, G);
}

// round 8
// speedup vs baseline: 2.0204x; 2.0204x over previous
#include <cuda_runtime.h>
#include <cuda_fp16.h>
#include <cstdint>

// Problem-size maxima (fixed by the reference generator).
static constexpr int NMAX = 1000000;
static constexpr int EMAX = 12000000;
static constexpr int GMAX = 1000;
static constexpr int PMAX = EMAX / 2 + 1;   // edge pairs

// Node state + aggregation buffer: 8 fp16 per node (16B, one LDG.128 gather,
// one red.global.add.v4.f16x2 scatter).
__device__ uint4 g_h  [NMAX];
__device__ uint4 g_agg[NMAX];
// fp16 edge_attr cache written by layer-1's edge pass, read by layers 2-3.
// Pair layout: eaA[t] = {e0.a01, e0.a23, e0.a45, e1.a01}, eaB[t] = {e1.a23, e1.a45}.
__device__ uint4 g_eaA[PMAX];
__device__ uint2 g_eaB[PMAX];
__device__ float g_gsum[GMAX];
__device__ float g_gcnt[GMAX];

__device__ __forceinline__ unsigned f2h2(float a, float b) {
    __half2 p = __floats2half2_rn(a, b);
    return *reinterpret_cast<unsigned*>(&p);
}
__device__ __forceinline__ float2 h22f2(unsigned u) {
    return __half22float2(*reinterpret_cast<__half2*>(&u));
}
__device__ __forceinline__ __half2 u2h(unsigned u) {
    return *reinterpret_cast<__half2*>(&u);
}
__device__ __forceinline__ unsigned h2u(__half2 h) {
    return *reinterpret_cast<unsigned*>(&h);
}
__device__ __forceinline__ uint4 pack_h(const float* v) {
    return make_uint4(f2h2(v[0], v[1]), f2h2(v[2], v[3]), f2h2(v[4], v[5]), 0u);
}
__device__ __forceinline__ void unpack_h(uint4 v, float* a) {
    float2 f0 = h22f2(v.x), f1 = h22f2(v.y), f2 = h22f2(v.z);
    a[0] = f0.x; a[1] = f0.y; a[2] = f1.x; a[3] = f1.y; a[4] = f2.x; a[5] = f2.y;
}

__device__ __forceinline__ void red_agg(int d, unsigned m01, unsigned m23, unsigned m45) {
    unsigned long long ap =
        (unsigned long long)__cvta_generic_to_global(&g_agg[d]);
    asm volatile("red.global.add.noftz.v4.f16x2 [%0], {%1,%2,%3,%4};"
                 :: "l"(ap), "r"(m01), "r"(m23), "r"(m45), "r"(0u) : "memory");
}

// ---------------------------------------------------------------------------
// Init: h <- fp16(x), agg <- 0, pool accumulators <- 0.
// ---------------------------------------------------------------------------
__global__ __launch_bounds__(256) void init_kernel(const float* __restrict__ x,
                                                   int N, int G) {
    int i = blockIdx.x * 256 + threadIdx.x;
    if (i < N) {
        const float2* xp = reinterpret_cast<const float2*>(x + (size_t)i * 6);
        float2 a = __ldcs(xp + 0);
        float2 b = __ldcs(xp + 1);
        float2 c = __ldcs(xp + 2);
        float v[6] = {a.x, a.y, b.x, b.y, c.x, c.y};
        g_h[i]   = pack_h(v);
        g_agg[i] = make_uint4(0u, 0u, 0u, 0u);
    }
    if (i < G) { g_gsum[i] = 0.f; g_gcnt[i] = 0.f; }
}

// ---------------------------------------------------------------------------
// Layer-1 edge pass (2 edges/thread): m = relu(h[src] + ea_fp32);
// agg[dst] += fp16(m). Also writes ea as fp16 (coalesced .cs) for layers 2-3.
// ---------------------------------------------------------------------------
__global__ __launch_bounds__(256) void edge1_kernel(const int* __restrict__ ei,
                                                    const float* __restrict__ ea,
                                                    int E) {
    int t = blockIdx.x * 256 + threadIdx.x;
    int e0 = t * 2;
    if (e0 >= E) return;
    bool has1 = (e0 + 1 < E);

    int s0 = __ldcs(ei + e0);
    int d0 = __ldcs(ei + (size_t)E + e0);
    int s1 = has1 ? __ldcs(ei + e0 + 1) : 0;
    int d1 = has1 ? __ldcs(ei + (size_t)E + e0 + 1) : 0;

    const float2* ep0 = reinterpret_cast<const float2*>(ea + (size_t)e0 * 6);
    float2 p00 = __ldcs(ep0 + 0), p01 = __ldcs(ep0 + 1), p02 = __ldcs(ep0 + 2);
    float2 p10 = make_float2(0.f, 0.f), p11 = p10, p12 = p10;
    if (has1) {
        const float2* ep1 = ep0 + 3;
        p10 = __ldcs(ep1 + 0); p11 = __ldcs(ep1 + 1); p12 = __ldcs(ep1 + 2);
    }

    uint4 hv0 = __ldg(&g_h[s0]);
    uint4 hv1 = has1 ? __ldg(&g_h[s1]) : make_uint4(0u, 0u, 0u, 0u);

    float h0[6]; unpack_h(hv0, h0);
    {
        unsigned m01 = f2h2(fmaxf(h0[0] + p00.x, 0.f), fmaxf(h0[1] + p00.y, 0.f));
        unsigned m23 = f2h2(fmaxf(h0[2] + p01.x, 0.f), fmaxf(h0[3] + p01.y, 0.f));
        unsigned m45 = f2h2(fmaxf(h0[4] + p02.x, 0.f), fmaxf(h0[5] + p02.y, 0.f));
        red_agg(d0, m01, m23, m45);
    }
    unsigned ea1_01 = 0u, ea1_23 = 0u, ea1_45 = 0u;
    if (has1) {
        float h1[6]; unpack_h(hv1, h1);
        unsigned m01 = f2h2(fmaxf(h1[0] + p10.x, 0.f), fmaxf(h1[1] + p10.y, 0.f));
        unsigned m23 = f2h2(fmaxf(h1[2] + p11.x, 0.f), fmaxf(h1[3] + p11.y, 0.f));
        unsigned m45 = f2h2(fmaxf(h1[4] + p12.x, 0.f), fmaxf(h1[5] + p12.y, 0.f));
        red_agg(d1, m01, m23, m45);
        ea1_01 = f2h2(p10.x, p10.y);
        ea1_23 = f2h2(p11.x, p11.y);
        ea1_45 = f2h2(p12.x, p12.y);
    }

    // fp16 ea cache for layers 2-3 (coalesced streaming stores).
    uint4 A = make_uint4(f2h2(p00.x, p00.y), f2h2(p01.x, p01.y),
                         f2h2(p02.x, p02.y), ea1_01);
    uint2 B = make_uint2(ea1_23, ea1_45);
    __stcs(&g_eaA[t], A);
    __stcs(&g_eaB[t], B);
}

// ---------------------------------------------------------------------------
// Layers 2-3 edge pass (2 edges/thread): pure fp16 message math
// (HADD2 gives the identical correctly-rounded result as fp32-add + round).
// ---------------------------------------------------------------------------
__global__ __launch_bounds__(256) void edge23_kernel(const int* __restrict__ ei,
                                                     int E) {
    int t = blockIdx.x * 256 + threadIdx.x;
    int e0 = t * 2;
    if (e0 >= E) return;
    bool has1 = (e0 + 1 < E);

    int s0 = __ldcs(ei + e0);
    int d0 = __ldcs(ei + (size_t)E + e0);
    int s1 = has1 ? __ldcs(ei + e0 + 1) : 0;
    int d1 = has1 ? __ldcs(ei + (size_t)E + e0 + 1) : 0;

    uint4 A = __ldcs(&g_eaA[t]);
    uint2 B = __ldcs(&g_eaB[t]);

    uint4 hv0 = __ldg(&g_h[s0]);
    uint4 hv1 = has1 ? __ldg(&g_h[s1]) : make_uint4(0u, 0u, 0u, 0u);

    __half2 z = __float2half2_rn(0.f);
    {
        __half2 m01 = __hmax2(__hadd2(u2h(hv0.x), u2h(A.x)), z);
        __half2 m23 = __hmax2(__hadd2(u2h(hv0.y), u2h(A.y)), z);
        __half2 m45 = __hmax2(__hadd2(u2h(hv0.z), u2h(A.z)), z);
        red_agg(d0, h2u(m01), h2u(m23), h2u(m45));
    }
    if (has1) {
        __half2 m01 = __hmax2(__hadd2(u2h(hv1.x), u2h(A.w)), z);
        __half2 m23 = __hmax2(__hadd2(u2h(hv1.y), u2h(B.x)), z);
        __half2 m45 = __hmax2(__hadd2(u2h(hv1.z), u2h(B.y)), z);
        red_agg(d1, h2u(m01), h2u(m23), h2u(m45));
    }
}

// ---------------------------------------------------------------------------
// Node update: h <- fp16(relu((h + agg) @ W + b)); agg <- 0.
// ---------------------------------------------------------------------------
__global__ __launch_bounds__(256) void node_kernel(const float* __restrict__ W,
                                                   const float* __restrict__ b,
                                                   int N) {
    __shared__ float sW[36];
    __shared__ float sb[6];
    if (threadIdx.x < 36) sW[threadIdx.x] = W[threadIdx.x];
    if (threadIdx.x < 6)  sb[threadIdx.x] = b[threadIdx.x];
    __syncthreads();

    int i = blockIdx.x * 256 + threadIdx.x;
    if (i >= N) return;

    float h[6], a[6];
    unpack_h(g_h[i], h);
    unpack_h(g_agg[i], a);

    float t[6] = {h[0] + a[0], h[1] + a[1], h[2] + a[2],
                  h[3] + a[3], h[4] + a[4], h[5] + a[5]};
    float y[6];
#pragma unroll
    for (int j = 0; j < 6; j++) {
        float acc = sb[j];
#pragma unroll
        for (int k = 0; k < 6; k++) acc = fmaf(t[k], sW[k * 6 + j], acc);
        y[j] = fmaxf(acc, 0.f);
    }

    g_h[i]   = pack_h(y);
    g_agg[i] = make_uint4(0u, 0u, 0u, 0u);
}

// ---------------------------------------------------------------------------
// Layer-3 node update fused with pooling head:
//   y = (h + agg) @ W3 + b3 (no relu);  s = y . Wl
//   pooled@Wl = (sum_i s_i)/cnt  -> accumulate (s, 1) per graph.
// batch (int32, sorted) -> warp-segmented reduction, ~1 atomic per run.
// ---------------------------------------------------------------------------
__global__ __launch_bounds__(256) void node3_kernel(const float* __restrict__ W,
                                                    const float* __restrict__ b,
                                                    const float* __restrict__ Wl,
                                                    const int* __restrict__ batch,
                                                    int N) {
    __shared__ float sW[36];
    __shared__ float sb[6];
    __shared__ float sWl[6];
    if (threadIdx.x < 36) sW[threadIdx.x] = W[threadIdx.x];
    if (threadIdx.x < 6) { sb[threadIdx.x] = b[threadIdx.x]; sWl[threadIdx.x] = Wl[threadIdx.x]; }
    __syncthreads();

    int i = blockIdx.x * 256 + threadIdx.x;
    float s = 0.f, c = 0.f;
    int g = -1;
    if (i < N) {
        float h[6], a[6];
        unpack_h(g_h[i], h);
        unpack_h(g_agg[i], a);
        float t[6] = {h[0] + a[0], h[1] + a[1], h[2] + a[2],
                      h[3] + a[3], h[4] + a[4], h[5] + a[5]};
#pragma unroll
        for (int j = 0; j < 6; j++) {
            float acc = sb[j];
#pragma unroll
            for (int k = 0; k < 6; k++) acc = fmaf(t[k], sW[k * 6 + j], acc);
            s = fmaf(acc, sWl[j], s);
        }
        c = 1.f;
        g = __ldg(batch + i);
    }

    // Segmented suffix reduction over sorted keys within the warp.
    int lane = threadIdx.x & 31;
#pragma unroll
    for (int off = 1; off < 32; off <<= 1) {
        float ov = __shfl_down_sync(0xFFFFFFFFu, s, off);
        float oc = __shfl_down_sync(0xFFFFFFFFu, c, off);
        int   og = __shfl_down_sync(0xFFFFFFFFu, g, off);
        if (lane + off < 32 && og == g) { s += ov; c += oc; }
    }
    int gprev = __shfl_up_sync(0xFFFFFFFFu, g, 1);
    bool head = (lane == 0) || (gprev != g);
    if (head && g >= 0) {
        atomicAdd(&g_gsum[g], s);
        atomicAdd(&g_gcnt[g], c);
    }
}

// ---------------------------------------------------------------------------
// Finalize: out[g] = gsum[g] / max(cnt, 1) + bl
// ---------------------------------------------------------------------------
__global__ __launch_bounds__(256) void final_kernel(const float* __restrict__ bl,
                                                    float* __restrict__ out, int G) {
    int g = blockIdx.x * 256 + threadIdx.x;
    if (g < G) out[g] = g_gsum[g] / fmaxf(g_gcnt[g], 1.f) + bl[0];
}

// ---------------------------------------------------------------------------
extern "C" void kernel_launch(void* const* d_in, const int* in_sizes, int n_in,
                              void* d_out, int out_size) {
    const float* x     = (const float*)d_in[0];
    const int*   ei    = (const int*)d_in[1];     // int32 (JAX x64 disabled)
    const float* ea    = (const float*)d_in[2];
    const int*   batch = (const int*)d_in[3];     // int32
    const float* W1 = (const float*)d_in[4];
    const float* b1 = (const float*)d_in[5];
    const float* W2 = (const float*)d_in[6];
    const float* b2 = (const float*)d_in[7];
    const float* W3 = (const float*)d_in[8];
    const float* b3 = (const float*)d_in[9];
    const float* Wl = (const float*)d_in[10];
    const float* bl = (const float*)d_in[11];
    float* out = (float*)d_out;

    int N = in_sizes[0] / 6;   // x is [N, 6]
    int E = in_sizes[2] / 6;   // edge_attr is [E, 6]
    int G = out_size;          // out is [G, 1]

    int nb = (N + 255) / 256;
    int pb = (((E + 1) / 2) + 255) / 256;  // edge-pair blocks
    int gb = (G + 255) / 256;

    init_kernel<<<nb, 256>>>(x, N, G);

    edge1_kernel<<<pb, 256>>>(ei, ea, E);
    node_kernel<<<nb, 256>>>(W1, b1, N);

    edge23_kernel<<<pb, 256>>>(ei, E);
    node_kernel<<<nb, 256>>>(W2, b2, N);

    edge23_kernel<<<pb, 256>>>(ei, E);
    node3_kernel<<<nb, 256>>>(W3, b3, Wl, batch, N);

    final_kernel<<<gb, 256>>>(bl, out, G);
}